// round 10
// baseline (speedup 1.0000x reference)
#include <cuda_runtime.h>
#include <cstdint>

constexpr int N_IN    = 256;
constexpr int BATCH   = 4096;
constexpr int TPB     = 256;
constexpr int NB      = 8;      // batches per block
constexpr int TILE_F4 = 1024;   // float4 per batch (16 KB)
constexpr int TILE_B  = 16384;  // bytes per batch

__device__ __forceinline__ uint32_t s2u(const void* p) {
    return (uint32_t)__cvta_generic_to_shared(p);
}

__device__ __forceinline__ void mbar_init(uint32_t mbar, uint32_t count) {
    asm volatile("mbarrier.init.shared.b64 [%0], %1;" :: "r"(mbar), "r"(count) : "memory");
}
__device__ __forceinline__ void mbar_expect_tx(uint32_t mbar, uint32_t bytes) {
    asm volatile("mbarrier.arrive.expect_tx.shared.b64 _, [%0], %1;" :: "r"(mbar), "r"(bytes) : "memory");
}
__device__ __forceinline__ void mbar_wait(uint32_t mbar, uint32_t parity) {
    asm volatile(
        "{\n\t"
        ".reg .pred P;\n\t"
        "WL%=:\n\t"
        "mbarrier.try_wait.parity.acquire.cta.shared::cta.b64 P, [%0], %1, 0x989680;\n\t"
        "@!P bra WL%=;\n\t"
        "}"
        :: "r"(mbar), "r"(parity) : "memory");
}
__device__ __forceinline__ void bulk_load(uint32_t smem_dst, const void* gmem_src,
                                          uint32_t bytes, uint32_t mbar) {
    asm volatile("cp.async.bulk.shared::cta.global.mbarrier::complete_tx::bytes [%0], [%1], %2, [%3];"
                 :: "r"(smem_dst), "l"(gmem_src), "r"(bytes), "r"(mbar) : "memory");
}
__device__ __forceinline__ void bulk_store(void* gmem_dst, uint32_t smem_src, uint32_t bytes) {
    asm volatile("cp.async.bulk.global.shared::cta.bulk_group [%0], [%1], %2;"
                 :: "l"(gmem_dst), "r"(smem_src), "r"(bytes) : "memory");
}

__global__ void __launch_bounds__(TPB) fused_kernel(
    const float4* __restrict__ I,
    const float*  __restrict__ aW,
    const float*  __restrict__ uW,
    const float*  __restrict__ tW,
    float4* __restrict__ O)
{
    extern __shared__ float4 smem[];           // [2][1024] in, [2][1024] out
    float4* s_in  = smem;                      // 32 KB
    float4* s_out = smem + 2 * TILE_F4;        // 32 KB
    __shared__ __align__(8) uint64_t mbar_s[2];

    const int tid = threadIdx.x;

    // ---- prologue: build 4 WMs per thread (rows tid+256p -> matrix (tid>>2)+64p) ----
    float4 W[4][3];   // rows 0..2; row3 = (0,0,0,1) implicit
#pragma unroll
    for (int p = 0; p < 4; p++) {
        const int n = (tid >> 2) + 64 * p;
        float a  = aW[n];
        float ux = __frcp_rn(1.0f + __expf(-uW[n * 3 + 0]));
        float uy = __frcp_rn(1.0f + __expf(-uW[n * 3 + 1]));
        float uz = __frcp_rn(1.0f + __expf(-uW[n * 3 + 2]));
        float inv = rsqrtf(fmaf(ux, ux, fmaf(uy, uy, uz * uz)));
        ux *= inv; uy *= inv; uz *= inv;
        float s = __sinf(a), c = __cosf(a);

        W[p][0] = make_float4((1.0f - ux * ux) * c + ux * ux,
                              -uz * s - ux * uy * c + ux * uy,
                               uy * s - ux * uz * c + ux * uz,
                               tW[n * 3 + 0]);
        W[p][1] = make_float4( uz * s - ux * uy * c + ux * uy,
                              (1.0f - uy * uy) * c + uy * uy,
                              -ux * s - uy * uz * c + uy * uz,
                               tW[n * 3 + 1]);
        W[p][2] = make_float4(-uy * s - ux * uz * c + ux * uz,
                               ux * s - uy * uz * c + uy * uz,
                              (1.0f - uz * uz) * c + uz * uz,
                               tW[n * 3 + 2]);
    }

    const uint32_t mb0 = s2u(&mbar_s[0]);
    const uint32_t mb1 = s2u(&mbar_s[1]);
    const uint32_t in_u  = s2u(s_in);
    const uint32_t out_u = s2u(s_out);

    if (tid == 0) {
        mbar_init(mb0, 1);
        mbar_init(mb1, 1);
    }
    __syncthreads();

    const float4* Ig = I + (size_t)blockIdx.x * NB * TILE_F4;
    float4*       Og = O + (size_t)blockIdx.x * NB * TILE_F4;

    // prefetch batches 0, 1
    if (tid == 0) {
        mbar_expect_tx(mb0, TILE_B);
        bulk_load(in_u, Ig, TILE_B, mb0);
        mbar_expect_tx(mb1, TILE_B);
        bulk_load(in_u + TILE_B, Ig + TILE_F4, TILE_B, mb1);
    }

#pragma unroll
    for (int j = 0; j < NB; j++) {
        const int s = j & 1;
        mbar_wait(s ? mb1 : mb0, (j >> 1) & 1);

        // out[s] must be free: store from batch j-2 finished reading smem
        if (j >= 2 && tid == 0)
            asm volatile("cp.async.bulk.wait_group.read 1;" ::: "memory");
        __syncthreads();

        const float4* in  = s_in  + s * TILE_F4;
        float4*       out = s_out + s * TILE_F4;

#pragma unroll
        for (int p = 0; p < 4; p++) {
            float4 v = in[tid + 256 * p];
            float4 o;
            o.x = fmaf(v.x, W[p][0].x, fmaf(v.y, W[p][1].x, v.z * W[p][2].x));
            o.y = fmaf(v.x, W[p][0].y, fmaf(v.y, W[p][1].y, v.z * W[p][2].y));
            o.z = fmaf(v.x, W[p][0].z, fmaf(v.y, W[p][1].z, v.z * W[p][2].z));
            o.w = fmaf(v.x, W[p][0].w, fmaf(v.y, W[p][1].w, fmaf(v.z, W[p][2].w, v.w)));
            out[tid + 256 * p] = o;
        }
        __syncthreads();   // all STS done; all LDS of in[s] done

        if (tid == 0) {
            asm volatile("fence.proxy.async.shared::cta;" ::: "memory");
            bulk_store(Og + (size_t)j * TILE_F4, out_u + s * TILE_B, TILE_B);
            asm volatile("cp.async.bulk.commit_group;" ::: "memory");
            if (j + 2 < NB) {
                const uint32_t mb = s ? mb1 : mb0;
                mbar_expect_tx(mb, TILE_B);
                bulk_load(in_u + s * TILE_B, Ig + (size_t)(j + 2) * TILE_F4, TILE_B, mb);
            }
        }
    }

    // drain outstanding stores before exit
    if (tid == 0)
        asm volatile("cp.async.bulk.wait_group 0;" ::: "memory");
}

extern "C" void kernel_launch(void* const* d_in, const int* in_sizes, int n_in,
                              void* d_out, int out_size) {
    const float* I  = (const float*)d_in[0];
    const float* aW = (const float*)d_in[1];
    const float* uW = (const float*)d_in[2];
    const float* tW = (const float*)d_in[3];

    static bool attr_set = false;
    if (!attr_set) {
        cudaFuncSetAttribute(fused_kernel,
                             cudaFuncAttributeMaxDynamicSharedMemorySize, 65536);
        attr_set = true;
    }

    int blocks = BATCH / NB;   // 512
    fused_kernel<<<blocks, TPB, 65536>>>((const float4*)I, aW, uW, tW, (float4*)d_out);
}

// round 11
// speedup vs baseline: 1.4374x; 1.4374x over previous
#include <cuda_runtime.h>
#include <cstdint>

constexpr int N_IN  = 256;
constexpr int BATCH = 4096;
constexpr int ITER  = 16;
constexpr int GRP   = 8;     // batches per load-burst (true MLP=8)
constexpr int TPB   = 256;   // 128 matrices * 2 row-pairs per block
constexpr int HALF  = 128;   // matrices per block

struct V8 { uint32_t r[8]; };

// volatile: pin issue order — force all GRP loads in flight before compute
__device__ __forceinline__ V8 ldg256_el(const void* p) {
    V8 v;
    asm volatile("ld.global.nc.L2::evict_last.v8.b32 {%0,%1,%2,%3,%4,%5,%6,%7}, [%8];"
                 : "=r"(v.r[0]), "=r"(v.r[1]), "=r"(v.r[2]), "=r"(v.r[3]),
                   "=r"(v.r[4]), "=r"(v.r[5]), "=r"(v.r[6]), "=r"(v.r[7])
                 : "l"(p));
    return v;
}
__device__ __forceinline__ void stg256_ef(void* p, const V8& v) {
    asm volatile("st.global.L2::evict_first.v8.b32 [%0], {%1,%2,%3,%4,%5,%6,%7,%8};"
                 :: "l"(p),
                    "r"(v.r[0]), "r"(v.r[1]), "r"(v.r[2]), "r"(v.r[3]),
                    "r"(v.r[4]), "r"(v.r[5]), "r"(v.r[6]), "r"(v.r[7])
                 : "memory");
}

__global__ void __launch_bounds__(TPB, 3) fused_kernel(
    const float* __restrict__ I,
    const float* __restrict__ aW,
    const float* __restrict__ uW,
    const float* __restrict__ tW,
    float* __restrict__ O)
{
    const int tid = threadIdx.x;
    const int h   = blockIdx.x & 1;           // which half of N_IN
    const int g   = blockIdx.x >> 1;          // batch group (0..255)

    // ---- build WM[n] in registers (MUFU fast path) ----
    const int n = h * HALF + (tid >> 1);

    float a  = aW[n];
    float ex = __expf(-uW[n * 3 + 0]);
    float ey = __expf(-uW[n * 3 + 1]);
    float ez = __expf(-uW[n * 3 + 2]);
    float ux = __frcp_rn(1.0f + ex);
    float uy = __frcp_rn(1.0f + ey);
    float uz = __frcp_rn(1.0f + ez);
    float inv = rsqrtf(fmaf(ux, ux, fmaf(uy, uy, uz * uz)));
    ux *= inv; uy *= inv; uz *= inv;

    float s = __sinf(a);
    float c = __cosf(a);

    // rows of WM; row3 = (0,0,0,1) handled implicitly in the FMA tree
    float4 r0, r1, r2;
    r0.x = (1.0f - ux * ux) * c + ux * ux;
    r0.y = -uz * s - ux * uy * c + ux * uy;
    r0.z =  uy * s - ux * uz * c + ux * uz;
    r0.w = tW[n * 3 + 0];
    r1.x =  uz * s - ux * uy * c + ux * uy;
    r1.y = (1.0f - uy * uy) * c + uy * uy;
    r1.z = -ux * s - uy * uz * c + uy * uz;
    r1.w = tW[n * 3 + 1];
    r2.x = -uy * s - ux * uz * c + ux * uz;
    r2.y =  ux * s - uy * uz * c + uy * uz;
    r2.z = (1.0f - uz * uz) * c + uz * uz;
    r2.w = tW[n * 3 + 2];

    // ---- stream ITER batches in bursts of GRP=8 volatile loads ----
    constexpr int STRIDE_F = N_IN * 16;        // 4096 floats per batch
    int fidx = g * (ITER * STRIDE_F) + n * 16 + (tid & 1) * 8;

#pragma unroll
    for (int jj = 0; jj < ITER / GRP; jj++) {
        V8 in[GRP];
#pragma unroll
        for (int k = 0; k < GRP; k++) in[k] = ldg256_el(I + fidx + k * STRIDE_F);

#pragma unroll
        for (int k = 0; k < GRP; k++) {
            V8 ov;
#pragma unroll
            for (int half = 0; half < 2; half++) {
                float vx = __uint_as_float(in[k].r[half * 4 + 0]);
                float vy = __uint_as_float(in[k].r[half * 4 + 1]);
                float vz = __uint_as_float(in[k].r[half * 4 + 2]);
                float vw = __uint_as_float(in[k].r[half * 4 + 3]);
                ov.r[half * 4 + 0] = __float_as_uint(fmaf(vx, r0.x, fmaf(vy, r1.x, vz * r2.x)));
                ov.r[half * 4 + 1] = __float_as_uint(fmaf(vx, r0.y, fmaf(vy, r1.y, vz * r2.y)));
                ov.r[half * 4 + 2] = __float_as_uint(fmaf(vx, r0.z, fmaf(vy, r1.z, vz * r2.z)));
                ov.r[half * 4 + 3] = __float_as_uint(fmaf(vx, r0.w, fmaf(vy, r1.w, fmaf(vz, r2.w, vw))));
            }
            stg256_ef(O + fidx + k * STRIDE_F, ov);
        }
        fidx += GRP * STRIDE_F;
    }
}

extern "C" void kernel_launch(void* const* d_in, const int* in_sizes, int n_in,
                              void* d_out, int out_size) {
    const float* I  = (const float*)d_in[0];
    const float* aW = (const float*)d_in[1];
    const float* uW = (const float*)d_in[2];
    const float* tW = (const float*)d_in[3];

    int blocks = (BATCH / ITER) * 2;   // 512
    fused_kernel<<<blocks, TPB>>>(I, aW, uW, tW, (float*)d_out);
}

// round 13
// speedup vs baseline: 1.5883x; 1.1050x over previous
#include <cuda_runtime.h>
#include <cstdint>

constexpr int N_IN  = 256;
constexpr int BATCH = 4096;
constexpr int ITER  = 16;
constexpr int GRP   = 8;     // batches per burst
constexpr int TPB   = 128;   // 64 matrices * 2 row-pairs per block
constexpr int QUART = 64;    // matrices per block

struct V8 { uint32_t r[8]; };

// non-volatile: let ptxas schedule (R9 proved this beats pinned order)
__device__ __forceinline__ V8 ldg256_el(const void* p) {
    V8 v;
    asm("ld.global.nc.L2::evict_last.v8.b32 {%0,%1,%2,%3,%4,%5,%6,%7}, [%8];"
        : "=r"(v.r[0]), "=r"(v.r[1]), "=r"(v.r[2]), "=r"(v.r[3]),
          "=r"(v.r[4]), "=r"(v.r[5]), "=r"(v.r[6]), "=r"(v.r[7])
        : "l"(p));
    return v;
}
__device__ __forceinline__ void stg256_ef(void* p, const V8& v) {
    asm volatile("st.global.L2::evict_first.v8.b32 [%0], {%1,%2,%3,%4,%5,%6,%7,%8};"
                 :: "l"(p),
                    "r"(v.r[0]), "r"(v.r[1]), "r"(v.r[2]), "r"(v.r[3]),
                    "r"(v.r[4]), "r"(v.r[5]), "r"(v.r[6]), "r"(v.r[7])
                 : "memory");
}

__global__ void __launch_bounds__(TPB) fused_kernel(
    const float* __restrict__ I,
    const float* __restrict__ aW,
    const float* __restrict__ uW,
    const float* __restrict__ tW,
    float* __restrict__ O)
{
    const int tid = threadIdx.x;
    const int q   = blockIdx.x & 3;           // which quarter of N_IN
    const int g   = blockIdx.x >> 2;          // batch group (0..255)

    // ---- build WM[n] in registers (MUFU fast path) ----
    const int n = q * QUART + (tid >> 1);

    float a  = aW[n];
    float ex = __expf(-uW[n * 3 + 0]);
    float ey = __expf(-uW[n * 3 + 1]);
    float ez = __expf(-uW[n * 3 + 2]);
    float ux = __frcp_rn(1.0f + ex);
    float uy = __frcp_rn(1.0f + ey);
    float uz = __frcp_rn(1.0f + ez);
    float inv = rsqrtf(fmaf(ux, ux, fmaf(uy, uy, uz * uz)));
    ux *= inv; uy *= inv; uz *= inv;

    float s = __sinf(a);
    float c = __cosf(a);

    // rows of WM; row3 = (0,0,0,1) folded into the FMA tree
    float4 r0, r1, r2;
    r0.x = (1.0f - ux * ux) * c + ux * ux;
    r0.y = -uz * s - ux * uy * c + ux * uy;
    r0.z =  uy * s - ux * uz * c + ux * uz;
    r0.w = tW[n * 3 + 0];
    r1.x =  uz * s - ux * uy * c + ux * uy;
    r1.y = (1.0f - uy * uy) * c + uy * uy;
    r1.z = -ux * s - uy * uz * c + uy * uz;
    r1.w = tW[n * 3 + 1];
    r2.x = -uy * s - ux * uz * c + ux * uz;
    r2.y =  ux * s - uy * uz * c + uy * uz;
    r2.z = (1.0f - uz * uz) * c + uz * uz;
    r2.w = tW[n * 3 + 2];

    // ---- stream ITER batches in bursts of GRP=8 ----
    constexpr int STRIDE_F = N_IN * 16;        // 4096 floats per batch
    int fidx = g * (ITER * STRIDE_F) + n * 16 + (tid & 1) * 8;

#pragma unroll
    for (int jj = 0; jj < ITER / GRP; jj++) {
        V8 in[GRP];
#pragma unroll
        for (int k = 0; k < GRP; k++) in[k] = ldg256_el(I + fidx + k * STRIDE_F);

#pragma unroll
        for (int k = 0; k < GRP; k++) {
            V8 ov;
#pragma unroll
            for (int half = 0; half < 2; half++) {
                float vx = __uint_as_float(in[k].r[half * 4 + 0]);
                float vy = __uint_as_float(in[k].r[half * 4 + 1]);
                float vz = __uint_as_float(in[k].r[half * 4 + 2]);
                float vw = __uint_as_float(in[k].r[half * 4 + 3]);
                ov.r[half * 4 + 0] = __float_as_uint(fmaf(vx, r0.x, fmaf(vy, r1.x, vz * r2.x)));
                ov.r[half * 4 + 1] = __float_as_uint(fmaf(vx, r0.y, fmaf(vy, r1.y, vz * r2.y)));
                ov.r[half * 4 + 2] = __float_as_uint(fmaf(vx, r0.z, fmaf(vy, r1.z, vz * r2.z)));
                ov.r[half * 4 + 3] = __float_as_uint(fmaf(vx, r0.w, fmaf(vy, r1.w, fmaf(vz, r2.w, vw))));
            }
            stg256_ef(O + fidx + k * STRIDE_F, ov);
        }
        fidx += GRP * STRIDE_F;
    }
}

extern "C" void kernel_launch(void* const* d_in, const int* in_sizes, int n_in,
                              void* d_out, int out_size) {
    const float* I  = (const float*)d_in[0];
    const float* aW = (const float*)d_in[1];
    const float* uW = (const float*)d_in[2];
    const float* tW = (const float*)d_in[3];

    int blocks = (BATCH / ITER) * 4;   // 1024
    fused_kernel<<<blocks, TPB>>>(I, aW, uW, tW, (float*)d_out);
}